// round 3
// baseline (speedup 1.0000x reference)
#include <cuda_runtime.h>
#include <cstdint>
#include <cstddef>

#define DEVINL __device__ __forceinline__

// ---------------- problem dims ----------------
constexpr int Bdim = 4, Tdim = 256, Udim = 64, Ddim = 512, Jdim = 1024, Vdim = 1024;

// ---------------- device scratch (allocs forbidden) ----------------
__device__ float g_enc_out[Bdim * Tdim * Jdim];   // 4 MB  [1024, 1024]
__device__ float g_pred_out[Bdim * Udim * Jdim];  // 1 MB  [256, 1024]
__device__ float g_Wt[Vdim * Jdim];               // 4 MB  W_out^T, tf32-rounded

// ---------------- PTX helpers (baseline ISA only: sm_80-level) ----------------
DEVINL uint32_t smem_u32(const void* p) {
    uint32_t a;
    asm("{ .reg .u64 t; cvta.to.shared.u64 t, %1; cvt.u32.u64 %0, t; }" : "=r"(a) : "l"(p));
    return a;
}
DEVINL void cp_async16(uint32_t dst, const void* src) {
    asm volatile("cp.async.ca.shared.global [%0], [%1], 16;" :: "r"(dst), "l"(src) : "memory");
}
DEVINL void cp_commit() { asm volatile("cp.async.commit_group;" ::: "memory"); }
DEVINL void cp_wait0() { asm volatile("cp.async.wait_group 0;" ::: "memory"); }

DEVINL void ldsm_x4(uint32_t& r0, uint32_t& r1, uint32_t& r2, uint32_t& r3, uint32_t addr) {
    asm volatile("ldmatrix.sync.aligned.m8n8.x4.shared.b16 {%0,%1,%2,%3}, [%4];"
                 : "=r"(r0), "=r"(r1), "=r"(r2), "=r"(r3) : "r"(addr));
}
DEVINL void mma_tf32(float& c0, float& c1, float& c2, float& c3,
                     uint32_t a0, uint32_t a1, uint32_t a2, uint32_t a3,
                     uint32_t b0, uint32_t b1) {
    asm volatile(
        "mma.sync.aligned.m16n8k8.row.col.f32.tf32.tf32.f32 "
        "{%0,%1,%2,%3}, {%4,%5,%6,%7}, {%8,%9}, {%0,%1,%2,%3};"
        : "+f"(c0), "+f"(c1), "+f"(c2), "+f"(c3)
        : "r"(a0), "r"(a1), "r"(a2), "r"(a3), "r"(b0), "r"(b1));
}
#define STS128(addr, r0, r1, r2, r3) \
    asm volatile("st.shared.v4.b32 [%0], {%1, %2, %3, %4};" \
                 :: "r"(addr), "r"(r0), "r"(r1), "r"(r2), "r"(r3) : "memory")

// accurate tanh (ex2.approx + rcp.approx, ~1e-6 rel), then rna->tf32
DEVINL uint32_t tanh_tf32(float x) {
    x = fminf(20.0f, fmaxf(-20.0f, x));
    float e;
    asm("ex2.approx.f32 %0, %1;" : "=f"(e) : "f"(x * 2.885390081777927f)); // 2*log2(e)
    float r;
    asm("rcp.approx.f32 %0, %1;" : "=f"(r) : "f"(e + 1.0f));
    float y = (e - 1.0f) * r;
    uint32_t u;
    asm("cvt.rna.tf32.f32 %0, %1;" : "=r"(u) : "f"(y));
    return u;
}

// ================= kernel 1: fp32 projection GEMM (C = X @ W + bias) =================
// X: [Mrows, 512], W: [512, 1024] row-major. which=0 -> g_enc_out, 1 -> g_pred_out.
__global__ __launch_bounds__(256) void proj_kernel(const float* __restrict__ X,
                                                   const float* __restrict__ W,
                                                   const float* __restrict__ bias,
                                                   int which) {
    float* __restrict__ C = which ? g_pred_out : g_enc_out;
    __shared__ float As[16][68];
    __shared__ float Bs[16][64];
    int tid = threadIdx.x;
    int m0 = blockIdx.y * 64;
    int n0 = blockIdx.x * 64;
    int ty = tid >> 4, tx = tid & 15;
    int a_m = tid >> 2, a_kq = tid & 3;
    int b_k = tid >> 4, b_nq = tid & 15;

    float acc[4][4];
#pragma unroll
    for (int i = 0; i < 4; ++i)
#pragma unroll
        for (int j = 0; j < 4; ++j) acc[i][j] = 0.0f;

    for (int k0 = 0; k0 < Ddim; k0 += 16) {
        float4 av = *(const float4*)(X + (size_t)(m0 + a_m) * Ddim + k0 + a_kq * 4);
        float4 bv = *(const float4*)(W + (size_t)(k0 + b_k) * Jdim + n0 + b_nq * 4);
        __syncthreads();
        As[a_kq * 4 + 0][a_m] = av.x;
        As[a_kq * 4 + 1][a_m] = av.y;
        As[a_kq * 4 + 2][a_m] = av.z;
        As[a_kq * 4 + 3][a_m] = av.w;
        *(float4*)&Bs[b_k][b_nq * 4] = bv;
        __syncthreads();
#pragma unroll
        for (int kk = 0; kk < 16; ++kk) {
            float a[4], b[4];
#pragma unroll
            for (int i = 0; i < 4; ++i) a[i] = As[kk][ty * 4 + i];
            float4 b4 = *(const float4*)&Bs[kk][tx * 4];
            b[0] = b4.x; b[1] = b4.y; b[2] = b4.z; b[3] = b4.w;
#pragma unroll
            for (int i = 0; i < 4; ++i)
#pragma unroll
                for (int j = 0; j < 4; ++j) acc[i][j] = fmaf(a[i], b[j], acc[i][j]);
        }
    }
#pragma unroll
    for (int i = 0; i < 4; ++i) {
#pragma unroll
        for (int j = 0; j < 4; ++j) {
            int n = n0 + tx * 4 + j;
            C[(size_t)(m0 + ty * 4 + i) * Jdim + n] = acc[i][j] + bias[n];
        }
    }
}

// ======== kernel 2: transpose W_out [J,V] -> g_Wt [V,J] with tf32 rounding ========
__global__ __launch_bounds__(256) void transpose_tf32_kernel(const float* __restrict__ W) {
    __shared__ float tile[32][33];
    int v0 = blockIdx.x * 32;
    int j0 = blockIdx.y * 32;
    int tx = threadIdx.x & 31;
    int ty = threadIdx.x >> 5;  // 0..7
#pragma unroll
    for (int i = 0; i < 32; i += 8)
        tile[ty + i][tx] = W[(size_t)(j0 + ty + i) * Vdim + v0 + tx];
    __syncthreads();
#pragma unroll
    for (int i = 0; i < 32; i += 8) {
        float x = tile[tx][ty + i];
        uint32_t u;
        asm("cvt.rna.tf32.f32 %0, %1;" : "=r"(u) : "f"(x));
        g_Wt[(size_t)(v0 + ty + i) * Jdim + j0 + tx] = __uint_as_float(u);
    }
}

// ================= kernel 3: fused tanh-joint @ W_out (mma.sync tf32) ==================
// CTA tile 128(M) x 256(N), K in 32 chunks of 32. 8 warps (2M x 4N), warp tile 64x64.
constexpr int BM = 128, BN = 256, KC = 32;
constexpr int AROW = 36;                       // floats per A smem row (pad 32->36)
constexpr int BROW = 36;
constexpr int ABYTES = BM * AROW * 4;          // 18432
constexpr int BBYTES = BN * BROW * 4;          // 36864
constexpr int OFF_BIAS = 0;
constexpr int OFF_A = 1024;
constexpr int OFF_B = OFF_A + 2 * ABYTES;      // 37888
constexpr int FUSED_SMEM = OFF_B + 2 * BBYTES; // 111616

__global__ __launch_bounds__(256, 1) void fused_joint_kernel(
    const float* __restrict__ b_out, float* __restrict__ out) {
    extern __shared__ char smem[];
    uint32_t sb = smem_u32(smem);
    float* bias_s = (float*)(smem + OFF_BIAS);

    int tid = threadIdx.x;
    int lane = tid & 31;
    int wid = tid >> 5;
    int wm = wid >> 2;        // 0..1
    int wn = wid & 3;         // 0..3

    int m0 = blockIdx.x << 7;          // M-tile base row
    int n0 = blockIdx.y << 8;          // N-tile base col
    int bidx = m0 >> 14;               // batch
    int t0 = (m0 >> 6) & (Tdim - 1);   // tile spans t-rows t0, t0+1 (u fastest)

    bias_s[tid] = b_out[n0 + tid];

    // ---- producer setup ----
    // A: 128 rows x 32 k per chunk; thread t handles row r = t>>1, k-half aq = t&1 (16 floats)
    int r = tid >> 1, aq = tid & 1;
    const float* eptr = g_enc_out + ((size_t)((bidx << 8) + t0 + (r >> 6)) << 10) + aq * 16;
    const float* pptr = g_pred_out + ((size_t)((bidx << 6) + (r & 63)) << 10) + aq * 16;
    uint32_t a_sts = sb + OFF_A + (uint32_t)r * (AROW * 4) + aq * 64;

    // B: 256 rows x 32 k per chunk via cp.async; thread handles 8 x 16B: row=(j*256+tid)>>3
    const float* bsrc = g_Wt + (size_t)(n0 + (tid >> 3)) * Jdim + (tid & 7) * 4;
    uint32_t b_sts = sb + OFF_B + (uint32_t)(tid >> 3) * (BROW * 4) + (tid & 7) * 16;

    // ---- consumer LDSM base offsets (per lane), +stage base +ks*32 at use ----
    int sub = lane >> 3;               // which 8x8 matrix this lane addresses
    int lrow = lane & 7;
    uint32_t a_off[4], b_off[4];
#pragma unroll
    for (int mt = 0; mt < 4; ++mt) {
        int row = wm * 64 + mt * 16 + (sub & 1) * 8 + lrow;
        a_off[mt] = (uint32_t)row * (AROW * 4) + (uint32_t)(sub >> 1) * 16;
    }
#pragma unroll
    for (int nt2 = 0; nt2 < 4; ++nt2) {
        int row = wn * 64 + nt2 * 16 + (sub & 1) * 8 + lrow;
        b_off[nt2] = (uint32_t)row * (BROW * 4) + (uint32_t)(sub >> 1) * 16;
    }

    float acc[4][8][4];
#pragma unroll
    for (int mt = 0; mt < 4; ++mt)
#pragma unroll
        for (int nt = 0; nt < 8; ++nt)
#pragma unroll
            for (int q = 0; q < 4; ++q) acc[mt][nt][q] = 0.0f;

    // ---- prologue: produce chunk 0 into stage 0 ----
    {
#pragma unroll
        for (int q2 = 0; q2 < 4; ++q2) {
            float4 e = *(const float4*)(eptr + q2 * 4);
            float4 p = *(const float4*)(pptr + q2 * 4);
            uint32_t o0 = tanh_tf32(e.x + p.x);
            uint32_t o1 = tanh_tf32(e.y + p.y);
            uint32_t o2 = tanh_tf32(e.z + p.z);
            uint32_t o3 = tanh_tf32(e.w + p.w);
            STS128(a_sts + q2 * 16, o0, o1, o2, o3);
        }
#pragma unroll
        for (int j = 0; j < 8; ++j)
            cp_async16(b_sts + j * 32 * (BROW * 4), bsrc + (size_t)j * 32 * Jdim);
        cp_commit();
    }

    // ---- main loop ----
#pragma unroll 1
    for (int c = 0; c < 32; ++c) {
        int s = c & 1;
        cp_wait0();
        __syncthreads();   // chunk c (A sts + B cp.async) visible; prev compute done

        if (c < 31) {
            int k1 = (c + 1) << 5;
            uint32_t a_dst = a_sts + (s ^ 1) * ABYTES;
#pragma unroll
            for (int q2 = 0; q2 < 4; ++q2) {
                float4 e = *(const float4*)(eptr + k1 + q2 * 4);
                float4 p = *(const float4*)(pptr + k1 + q2 * 4);
                uint32_t o0 = tanh_tf32(e.x + p.x);
                uint32_t o1 = tanh_tf32(e.y + p.y);
                uint32_t o2 = tanh_tf32(e.z + p.z);
                uint32_t o3 = tanh_tf32(e.w + p.w);
                STS128(a_dst + q2 * 16, o0, o1, o2, o3);
            }
            uint32_t b_dst = b_sts + (s ^ 1) * BBYTES;
#pragma unroll
            for (int j = 0; j < 8; ++j)
                cp_async16(b_dst + j * 32 * (BROW * 4), bsrc + k1 + (size_t)j * 32 * Jdim);
            cp_commit();
        }

        // compute chunk c from stage s
        uint32_t a_base = sb + OFF_A + s * ABYTES;
        uint32_t b_base = sb + OFF_B + s * BBYTES;
#pragma unroll
        for (int ks = 0; ks < 4; ++ks) {
            uint32_t a[4][4], b[4][4];
#pragma unroll
            for (int mt = 0; mt < 4; ++mt)
                ldsm_x4(a[mt][0], a[mt][1], a[mt][2], a[mt][3],
                        a_base + a_off[mt] + ks * 32);
#pragma unroll
            for (int nt2 = 0; nt2 < 4; ++nt2)
                ldsm_x4(b[nt2][0], b[nt2][1], b[nt2][2], b[nt2][3],
                        b_base + b_off[nt2] + ks * 32);
#pragma unroll
            for (int mt = 0; mt < 4; ++mt) {
#pragma unroll
                for (int nt2 = 0; nt2 < 4; ++nt2) {
                    mma_tf32(acc[mt][nt2 * 2][0], acc[mt][nt2 * 2][1],
                             acc[mt][nt2 * 2][2], acc[mt][nt2 * 2][3],
                             a[mt][0], a[mt][1], a[mt][2], a[mt][3],
                             b[nt2][0], b[nt2][2]);
                    mma_tf32(acc[mt][nt2 * 2 + 1][0], acc[mt][nt2 * 2 + 1][1],
                             acc[mt][nt2 * 2 + 1][2], acc[mt][nt2 * 2 + 1][3],
                             a[mt][0], a[mt][1], a[mt][2], a[mt][3],
                             b[nt2][1], b[nt2][3]);
                }
            }
        }
    }

    // ---- epilogue: bias + store ----
    int gr = lane >> 2, gc2 = (lane & 3) * 2;
    const float* bias_w = bias_s + wn * 64;
#pragma unroll
    for (int mt = 0; mt < 4; ++mt) {
#pragma unroll
        for (int half = 0; half < 2; ++half) {
            int row = m0 + wm * 64 + mt * 16 + gr + half * 8;
            float* orow = out + (size_t)row * Vdim + n0 + wn * 64;
#pragma unroll
            for (int nt = 0; nt < 8; ++nt) {
                int col = nt * 8 + gc2;
                float2 v;
                v.x = acc[mt][nt][half * 2 + 0] + bias_w[col];
                v.y = acc[mt][nt][half * 2 + 1] + bias_w[col + 1];
                *(float2*)(orow + col) = v;
            }
        }
    }
}

// ================= launch =================
extern "C" void kernel_launch(void* const* d_in, const int* in_sizes, int n_in,
                              void* d_out, int out_size) {
    const float* enc    = (const float*)d_in[0];
    const float* pred   = (const float*)d_in[1];
    const float* W_enc  = (const float*)d_in[2];
    const float* b_enc  = (const float*)d_in[3];
    const float* W_pred = (const float*)d_in[4];
    const float* b_pred = (const float*)d_in[5];
    const float* W_out  = (const float*)d_in[6];
    const float* b_out  = (const float*)d_in[7];
    float* out = (float*)d_out;

    cudaFuncSetAttribute(fused_joint_kernel,
                         cudaFuncAttributeMaxDynamicSharedMemorySize, FUSED_SMEM);

    // enc_out = enc @ W_enc + b_enc : M = B*T = 1024
    proj_kernel<<<dim3(Jdim / 64, 1024 / 64), 256>>>(enc, W_enc, b_enc, 0);
    // pred_out = pred @ W_pred + b_pred : M = B*U = 256
    proj_kernel<<<dim3(Jdim / 64, 256 / 64), 256>>>(pred, W_pred, b_pred, 1);
    // Wt = tf32(W_out^T)
    transpose_tf32_kernel<<<dim3(Vdim / 32, Jdim / 32), 256>>>(W_out);
    // fused joint GEMM: grid (M-tiles, N-tiles)
    fused_joint_kernel<<<dim3(512, 4), 256, FUSED_SMEM>>>(b_out, out);
}

// round 4
// speedup vs baseline: 1.4217x; 1.4217x over previous
#include <cuda_runtime.h>
#include <cuda_fp16.h>
#include <cstdint>
#include <cstddef>

#define DEVINL __device__ __forceinline__

// ---------------- problem dims ----------------
constexpr int Bdim = 4, Tdim = 256, Udim = 64, Ddim = 512, Jdim = 1024, Vdim = 1024;

// ---------------- device scratch (allocs forbidden) ----------------
__device__ float g_enc_out[Bdim * Tdim * Jdim];   // 4 MB  [1024, 1024]
__device__ float g_pred_out[Bdim * Udim * Jdim];  // 1 MB  [256, 1024]
__device__ __half g_Wth[Vdim * Jdim];             // 2 MB  W_out^T, fp16

// ---------------- PTX helpers (baseline ISA, sm_80-level) ----------------
DEVINL uint32_t smem_u32(const void* p) {
    uint32_t a;
    asm("{ .reg .u64 t; cvta.to.shared.u64 t, %1; cvt.u32.u64 %0, t; }" : "=r"(a) : "l"(p));
    return a;
}
DEVINL void cp_async16(uint32_t dst, const void* src) {
    asm volatile("cp.async.ca.shared.global [%0], [%1], 16;" :: "r"(dst), "l"(src) : "memory");
}
DEVINL void cp_commit() { asm volatile("cp.async.commit_group;" ::: "memory"); }
DEVINL void cp_wait0() { asm volatile("cp.async.wait_group 0;" ::: "memory"); }

DEVINL void ldsm_x4(uint32_t& r0, uint32_t& r1, uint32_t& r2, uint32_t& r3, uint32_t addr) {
    asm volatile("ldmatrix.sync.aligned.m8n8.x4.shared.b16 {%0,%1,%2,%3}, [%4];"
                 : "=r"(r0), "=r"(r1), "=r"(r2), "=r"(r3) : "r"(addr));
}
DEVINL void mma_fp16(float& c0, float& c1, float& c2, float& c3,
                     uint32_t a0, uint32_t a1, uint32_t a2, uint32_t a3,
                     uint32_t b0, uint32_t b1) {
    asm volatile(
        "mma.sync.aligned.m16n8k16.row.col.f32.f16.f16.f32 "
        "{%0,%1,%2,%3}, {%4,%5,%6,%7}, {%8,%9}, {%0,%1,%2,%3};"
        : "+f"(c0), "+f"(c1), "+f"(c2), "+f"(c3)
        : "r"(a0), "r"(a1), "r"(a2), "r"(a3), "r"(b0), "r"(b1));
}
#define STS128(addr, r0, r1, r2, r3) \
    asm volatile("st.shared.v4.b32 [%0], {%1, %2, %3, %4};" \
                 :: "r"(addr), "r"(r0), "r"(r1), "r"(r2), "r"(r3) : "memory")

// accurate tanh (ex2.approx + rcp.approx, ~1e-6 rel)
DEVINL float tanh_fast(float x) {
    x = fminf(20.0f, fmaxf(-20.0f, x));
    float e;
    asm("ex2.approx.f32 %0, %1;" : "=f"(e) : "f"(x * 2.885390081777927f)); // 2*log2(e)
    float r;
    asm("rcp.approx.f32 %0, %1;" : "=f"(r) : "f"(e + 1.0f));
    return (e - 1.0f) * r;
}
DEVINL uint32_t pack_h2(float lo, float hi) {
    __half2 h = __floats2half2_rn(lo, hi);
    return *(uint32_t*)&h;
}

// ================= kernel 1: fp32 projection GEMM (C = X @ W + bias) =================
__global__ __launch_bounds__(256) void proj_kernel(const float* __restrict__ X,
                                                   const float* __restrict__ W,
                                                   const float* __restrict__ bias,
                                                   int which) {
    float* __restrict__ C = which ? g_pred_out : g_enc_out;
    __shared__ float As[16][68];
    __shared__ float Bs[16][64];
    int tid = threadIdx.x;
    int m0 = blockIdx.y * 64;
    int n0 = blockIdx.x * 64;
    int ty = tid >> 4, tx = tid & 15;
    int a_m = tid >> 2, a_kq = tid & 3;
    int b_k = tid >> 4, b_nq = tid & 15;

    float acc[4][4];
#pragma unroll
    for (int i = 0; i < 4; ++i)
#pragma unroll
        for (int j = 0; j < 4; ++j) acc[i][j] = 0.0f;

    for (int k0 = 0; k0 < Ddim; k0 += 16) {
        float4 av = *(const float4*)(X + (size_t)(m0 + a_m) * Ddim + k0 + a_kq * 4);
        float4 bv = *(const float4*)(W + (size_t)(k0 + b_k) * Jdim + n0 + b_nq * 4);
        __syncthreads();
        As[a_kq * 4 + 0][a_m] = av.x;
        As[a_kq * 4 + 1][a_m] = av.y;
        As[a_kq * 4 + 2][a_m] = av.z;
        As[a_kq * 4 + 3][a_m] = av.w;
        *(float4*)&Bs[b_k][b_nq * 4] = bv;
        __syncthreads();
#pragma unroll
        for (int kk = 0; kk < 16; ++kk) {
            float a[4], b[4];
#pragma unroll
            for (int i = 0; i < 4; ++i) a[i] = As[kk][ty * 4 + i];
            float4 b4 = *(const float4*)&Bs[kk][tx * 4];
            b[0] = b4.x; b[1] = b4.y; b[2] = b4.z; b[3] = b4.w;
#pragma unroll
            for (int i = 0; i < 4; ++i)
#pragma unroll
                for (int j = 0; j < 4; ++j) acc[i][j] = fmaf(a[i], b[j], acc[i][j]);
        }
    }
#pragma unroll
    for (int i = 0; i < 4; ++i) {
#pragma unroll
        for (int j = 0; j < 4; ++j) {
            int n = n0 + tx * 4 + j;
            C[(size_t)(m0 + ty * 4 + i) * Jdim + n] = acc[i][j] + bias[n];
        }
    }
}

// ======== kernel 2: transpose W_out [J,V] -> g_Wth [V,J] in fp16 ========
__global__ __launch_bounds__(256) void transpose_h_kernel(const float* __restrict__ W) {
    __shared__ float tile[32][33];
    int v0 = blockIdx.x * 32;
    int j0 = blockIdx.y * 32;
    int tx = threadIdx.x & 31;
    int ty = threadIdx.x >> 5;  // 0..7
#pragma unroll
    for (int i = 0; i < 32; i += 8)
        tile[ty + i][tx] = W[(size_t)(j0 + ty + i) * Vdim + v0 + tx];
    __syncthreads();
#pragma unroll
    for (int i = 0; i < 32; i += 8)
        g_Wth[(size_t)(v0 + ty + i) * Jdim + j0 + tx] = __float2half_rn(tile[tx][ty + i]);
}

// ================= kernel 3: fused tanh-joint @ W_out (mma.sync fp16) ==================
// CTA tile 128(M) x 256(N), K=1024 in 32 chunks of 32. 8 warps (2M x 4N), warp tile 64x64.
constexpr int BM = 128, BN = 256;
constexpr int ARSTR = 80;                       // bytes per A smem row (64B data + 16B pad)
constexpr int BRSTR = 80;
constexpr int ABYTES = BM * ARSTR;              // 10240
constexpr int BBYTES = BN * BRSTR;              // 20480
constexpr int OFF_A = 1024;
constexpr int OFF_B = OFF_A + 2 * ABYTES;       // 21504
constexpr int FUSED_SMEM = OFF_B + 2 * BBYTES;  // 62464

__global__ __launch_bounds__(256, 1) void fused_joint_kernel(
    const float* __restrict__ b_out, float* __restrict__ out) {
    extern __shared__ char smem[];
    uint32_t sb = smem_u32(smem);
    float* bias_s = (float*)smem;

    int tid = threadIdx.x;
    int lane = tid & 31;
    int wid = tid >> 5;
    int wm = wid >> 2;        // 0..1
    int wn = wid & 3;         // 0..3

    int m0 = blockIdx.x << 7;          // M-tile base row
    int n0 = blockIdx.y << 8;          // N-tile base col
    int bidx = m0 >> 14;               // batch
    int t0 = (m0 >> 6) & (Tdim - 1);   // tile spans t-rows t0, t0+1 (u fastest)

    bias_s[tid] = b_out[n0 + tid];

    // ---- producer setup ----
    // A: thread t handles row r = t>>1, k-half aq = t&1 (16 floats -> 16 halfs = 32B)
    int r = tid >> 1, aq = tid & 1;
    const float* eptr = g_enc_out + ((size_t)((bidx << 8) + t0 + (r >> 6)) << 10) + aq * 16;
    const float* pptr = g_pred_out + ((size_t)((bidx << 6) + (r & 63)) << 10) + aq * 16;
    uint32_t a_sts = sb + OFF_A + (uint32_t)r * ARSTR + aq * 32;

    // B: 256 rows x 32 halfs per chunk via cp.async; 4 granules of 16B per thread
    const __half* bsrc = g_Wth + (size_t)(n0 + (tid >> 2)) * Jdim + (tid & 3) * 8;
    uint32_t b_sts = sb + OFF_B + (uint32_t)(tid >> 2) * BRSTR + (tid & 3) * 16;

    // ---- consumer LDSM per-lane offsets ----
    uint32_t a_off[4], b_off[4];
#pragma unroll
    for (int mt = 0; mt < 4; ++mt) {
        int row = wm * 64 + mt * 16 + (lane & 15);
        a_off[mt] = (uint32_t)row * ARSTR + (uint32_t)(lane >> 4) * 16;
    }
#pragma unroll
    for (int g = 0; g < 4; ++g) {
        int row = wn * 64 + g * 16 + (lane & 7) + ((lane >> 4) & 1) * 8;
        b_off[g] = (uint32_t)row * BRSTR + (uint32_t)((lane >> 3) & 1) * 16;
    }

    float acc[4][8][4];
#pragma unroll
    for (int mt = 0; mt < 4; ++mt)
#pragma unroll
        for (int nt = 0; nt < 8; ++nt)
#pragma unroll
            for (int q = 0; q < 4; ++q) acc[mt][nt][q] = 0.0f;

    // ---- prologue: produce chunk 0 into stage 0 ----
    {
#pragma unroll
        for (int j = 0; j < 4; ++j)
            cp_async16(b_sts + j * 64 * BRSTR, bsrc + (size_t)j * 64 * Jdim);
        cp_commit();
        uint32_t u[8];
#pragma unroll
        for (int q2 = 0; q2 < 4; ++q2) {
            float4 e = *(const float4*)(eptr + q2 * 4);
            float4 p = *(const float4*)(pptr + q2 * 4);
            u[q2 * 2 + 0] = pack_h2(tanh_fast(e.x + p.x), tanh_fast(e.y + p.y));
            u[q2 * 2 + 1] = pack_h2(tanh_fast(e.z + p.z), tanh_fast(e.w + p.w));
        }
        STS128(a_sts, u[0], u[1], u[2], u[3]);
        STS128(a_sts + 16, u[4], u[5], u[6], u[7]);
    }

    // ---- main loop ----
#pragma unroll 1
    for (int c = 0; c < 32; ++c) {
        int s = c & 1;
        cp_wait0();
        __syncthreads();   // chunk c staged; stage s^1 consumers (chunk c-1) done

        if (c < 31) {
            int k1 = (c + 1) << 5;
            // B first (no reg dependency) so the copy flies under the MMAs
            uint32_t b_dst = b_sts + (s ^ 1) * BBYTES;
#pragma unroll
            for (int j = 0; j < 4; ++j)
                cp_async16(b_dst + j * 64 * BRSTR, bsrc + k1 + (size_t)j * 64 * Jdim);
            cp_commit();
            // A: tanh(enc+pred) -> fp16
            uint32_t a_dst = a_sts + (s ^ 1) * ABYTES;
            uint32_t u[8];
#pragma unroll
            for (int q2 = 0; q2 < 4; ++q2) {
                float4 e = *(const float4*)(eptr + k1 + q2 * 4);
                float4 p = *(const float4*)(pptr + k1 + q2 * 4);
                u[q2 * 2 + 0] = pack_h2(tanh_fast(e.x + p.x), tanh_fast(e.y + p.y));
                u[q2 * 2 + 1] = pack_h2(tanh_fast(e.z + p.z), tanh_fast(e.w + p.w));
            }
            STS128(a_dst, u[0], u[1], u[2], u[3]);
            STS128(a_dst + 16, u[4], u[5], u[6], u[7]);
        }

        // compute chunk c from stage s: 2 k16 steps
        uint32_t a_base = sb + OFF_A + s * ABYTES;
        uint32_t b_base = sb + OFF_B + s * BBYTES;
#pragma unroll
        for (int ks = 0; ks < 2; ++ks) {
            uint32_t a[4][4], b[4][4];
#pragma unroll
            for (int mt = 0; mt < 4; ++mt)
                ldsm_x4(a[mt][0], a[mt][1], a[mt][2], a[mt][3],
                        a_base + a_off[mt] + ks * 32);
#pragma unroll
            for (int g = 0; g < 4; ++g)
                ldsm_x4(b[g][0], b[g][1], b[g][2], b[g][3],
                        b_base + b_off[g] + ks * 32);
#pragma unroll
            for (int mt = 0; mt < 4; ++mt) {
#pragma unroll
                for (int g = 0; g < 4; ++g) {
                    mma_fp16(acc[mt][g * 2][0], acc[mt][g * 2][1],
                             acc[mt][g * 2][2], acc[mt][g * 2][3],
                             a[mt][0], a[mt][1], a[mt][2], a[mt][3],
                             b[g][0], b[g][1]);
                    mma_fp16(acc[mt][g * 2 + 1][0], acc[mt][g * 2 + 1][1],
                             acc[mt][g * 2 + 1][2], acc[mt][g * 2 + 1][3],
                             a[mt][0], a[mt][1], a[mt][2], a[mt][3],
                             b[g][2], b[g][3]);
                }
            }
        }
    }

    // ---- epilogue: bias + store ----
    int gr = lane >> 2, gc2 = (lane & 3) * 2;
    const float* bias_w = bias_s + wn * 64;
#pragma unroll
    for (int mt = 0; mt < 4; ++mt) {
#pragma unroll
        for (int half = 0; half < 2; ++half) {
            int row = m0 + wm * 64 + mt * 16 + gr + half * 8;
            float* orow = out + (size_t)row * Vdim + n0 + wn * 64;
#pragma unroll
            for (int nt = 0; nt < 8; ++nt) {
                int col = nt * 8 + gc2;
                float2 v;
                v.x = acc[mt][nt][half * 2 + 0] + bias_w[col];
                v.y = acc[mt][nt][half * 2 + 1] + bias_w[col + 1];
                *(float2*)(orow + col) = v;
            }
        }
    }
}

// ================= launch =================
extern "C" void kernel_launch(void* const* d_in, const int* in_sizes, int n_in,
                              void* d_out, int out_size) {
    const float* enc    = (const float*)d_in[0];
    const float* pred   = (const float*)d_in[1];
    const float* W_enc  = (const float*)d_in[2];
    const float* b_enc  = (const float*)d_in[3];
    const float* W_pred = (const float*)d_in[4];
    const float* b_pred = (const float*)d_in[5];
    const float* W_out  = (const float*)d_in[6];
    const float* b_out  = (const float*)d_in[7];
    float* out = (float*)d_out;

    cudaFuncSetAttribute(fused_joint_kernel,
                         cudaFuncAttributeMaxDynamicSharedMemorySize, FUSED_SMEM);

    // enc_out = enc @ W_enc + b_enc : M = B*T = 1024
    proj_kernel<<<dim3(Jdim / 64, 1024 / 64), 256>>>(enc, W_enc, b_enc, 0);
    // pred_out = pred @ W_pred + b_pred : M = B*U = 256
    proj_kernel<<<dim3(Jdim / 64, 256 / 64), 256>>>(pred, W_pred, b_pred, 1);
    // Wt fp16 = W_out^T
    transpose_h_kernel<<<dim3(Vdim / 32, Jdim / 32), 256>>>(W_out);
    // fused joint GEMM: grid (M-tiles, N-tiles)
    fused_joint_kernel<<<dim3(512, 4), 256, FUSED_SMEM>>>(b_out, out);
}

// round 5
// speedup vs baseline: 1.9018x; 1.3377x over previous
#include <cuda_runtime.h>
#include <cuda_fp16.h>
#include <cstdint>
#include <cstddef>

#define DEVINL __device__ __forceinline__

// ---------------- problem dims ----------------
constexpr int Bdim = 4, Tdim = 256, Udim = 64, Ddim = 512, Jdim = 1024, Vdim = 1024;
constexpr int Mtot = Bdim * Tdim * Udim;  // 65536

// ---------------- device scratch (allocs forbidden) ----------------
__device__ float g_enc_out[Bdim * Tdim * Jdim];   // 4 MB  [1024, 1024]
__device__ float g_pred_out[Bdim * Udim * Jdim];  // 1 MB  [256, 1024]
__device__ __half g_Wth[Vdim * Jdim];             // 2 MB  W_out^T, fp16
__device__ __half g_Ah[(size_t)Mtot * Jdim];      // 134 MB  tanh(joint), fp16

// ---------------- PTX helpers (baseline ISA, sm_80-level) ----------------
DEVINL uint32_t smem_u32(const void* p) {
    uint32_t a;
    asm("{ .reg .u64 t; cvta.to.shared.u64 t, %1; cvt.u32.u64 %0, t; }" : "=r"(a) : "l"(p));
    return a;
}
DEVINL void cp_async16(uint32_t dst, const void* src) {
    asm volatile("cp.async.ca.shared.global [%0], [%1], 16;" :: "r"(dst), "l"(src) : "memory");
}
DEVINL void cp_commit() { asm volatile("cp.async.commit_group;" ::: "memory"); }
DEVINL void cp_wait2() { asm volatile("cp.async.wait_group 2;" ::: "memory"); }

DEVINL void ldsm_x4(uint32_t& r0, uint32_t& r1, uint32_t& r2, uint32_t& r3, uint32_t addr) {
    asm volatile("ldmatrix.sync.aligned.m8n8.x4.shared.b16 {%0,%1,%2,%3}, [%4];"
                 : "=r"(r0), "=r"(r1), "=r"(r2), "=r"(r3) : "r"(addr));
}
DEVINL void mma_fp16(float& c0, float& c1, float& c2, float& c3,
                     uint32_t a0, uint32_t a1, uint32_t a2, uint32_t a3,
                     uint32_t b0, uint32_t b1) {
    asm volatile(
        "mma.sync.aligned.m16n8k16.row.col.f32.f16.f16.f32 "
        "{%0,%1,%2,%3}, {%4,%5,%6,%7}, {%8,%9}, {%0,%1,%2,%3};"
        : "+f"(c0), "+f"(c1), "+f"(c2), "+f"(c3)
        : "r"(a0), "r"(a1), "r"(a2), "r"(a3), "r"(b0), "r"(b1));
}

// accurate tanh (ex2.approx + rcp.approx, ~1e-6 rel)
DEVINL float tanh_fast(float x) {
    x = fminf(20.0f, fmaxf(-20.0f, x));
    float e;
    asm("ex2.approx.f32 %0, %1;" : "=f"(e) : "f"(x * 2.885390081777927f)); // 2*log2(e)
    float r;
    asm("rcp.approx.f32 %0, %1;" : "=f"(r) : "f"(e + 1.0f));
    return (e - 1.0f) * r;
}
DEVINL uint32_t pack_h2(float lo, float hi) {
    __half2 h = __floats2half2_rn(lo, hi);
    return *(uint32_t*)&h;
}

// ================= kernel 1: fp32 projection GEMM (C = X @ W + bias) =================
__global__ __launch_bounds__(256) void proj_kernel(const float* __restrict__ X,
                                                   const float* __restrict__ W,
                                                   const float* __restrict__ bias,
                                                   int which) {
    float* __restrict__ C = which ? g_pred_out : g_enc_out;
    __shared__ float As[16][68];
    __shared__ float Bs[16][64];
    int tid = threadIdx.x;
    int m0 = blockIdx.y * 64;
    int n0 = blockIdx.x * 64;
    int ty = tid >> 4, tx = tid & 15;
    int a_m = tid >> 2, a_kq = tid & 3;
    int b_k = tid >> 4, b_nq = tid & 15;

    float acc[4][4];
#pragma unroll
    for (int i = 0; i < 4; ++i)
#pragma unroll
        for (int j = 0; j < 4; ++j) acc[i][j] = 0.0f;

    for (int k0 = 0; k0 < Ddim; k0 += 16) {
        float4 av = *(const float4*)(X + (size_t)(m0 + a_m) * Ddim + k0 + a_kq * 4);
        float4 bv = *(const float4*)(W + (size_t)(k0 + b_k) * Jdim + n0 + b_nq * 4);
        __syncthreads();
        As[a_kq * 4 + 0][a_m] = av.x;
        As[a_kq * 4 + 1][a_m] = av.y;
        As[a_kq * 4 + 2][a_m] = av.z;
        As[a_kq * 4 + 3][a_m] = av.w;
        *(float4*)&Bs[b_k][b_nq * 4] = bv;
        __syncthreads();
#pragma unroll
        for (int kk = 0; kk < 16; ++kk) {
            float a[4], b[4];
#pragma unroll
            for (int i = 0; i < 4; ++i) a[i] = As[kk][ty * 4 + i];
            float4 b4 = *(const float4*)&Bs[kk][tx * 4];
            b[0] = b4.x; b[1] = b4.y; b[2] = b4.z; b[3] = b4.w;
#pragma unroll
            for (int i = 0; i < 4; ++i)
#pragma unroll
                for (int j = 0; j < 4; ++j) acc[i][j] = fmaf(a[i], b[j], acc[i][j]);
        }
    }
#pragma unroll
    for (int i = 0; i < 4; ++i) {
#pragma unroll
        for (int j = 0; j < 4; ++j) {
            int n = n0 + tx * 4 + j;
            C[(size_t)(m0 + ty * 4 + i) * Jdim + n] = acc[i][j] + bias[n];
        }
    }
}

// ======== kernel 2: transpose W_out [J,V] -> g_Wth [V,J] in fp16 ========
__global__ __launch_bounds__(256) void transpose_h_kernel(const float* __restrict__ W) {
    __shared__ float tile[32][33];
    int v0 = blockIdx.x * 32;
    int j0 = blockIdx.y * 32;
    int tx = threadIdx.x & 31;
    int ty = threadIdx.x >> 5;  // 0..7
#pragma unroll
    for (int i = 0; i < 32; i += 8)
        tile[ty + i][tx] = W[(size_t)(j0 + ty + i) * Vdim + v0 + tx];
    __syncthreads();
#pragma unroll
    for (int i = 0; i < 32; i += 8)
        g_Wth[(size_t)(v0 + ty + i) * Jdim + j0 + tx] = __float2half_rn(tile[tx][ty + i]);
}

// ======== kernel 3: A_h[m][k] = fp16(tanh(enc_out[b,t,k] + pred_out[b,u,k])) ========
// one thread = 4 consecutive k. 65536 blocks x 256 threads.
__global__ __launch_bounds__(256) void tanh_pre_kernel() {
    size_t idx = (size_t)blockIdx.x * 256 + threadIdx.x;  // quad index
    int m = (int)(idx >> 8);
    int kc = ((int)idx & 255) * 4;
    int b = m >> 14, t = (m >> 6) & (Tdim - 1), u = m & (Udim - 1);
    const float* e = g_enc_out + ((size_t)((b << 8) + t) << 10) + kc;
    const float* p = g_pred_out + ((size_t)((b << 6) + u) << 10) + kc;
    float4 ev = *(const float4*)e;
    float4 pv = *(const float4*)p;
    uint2 o;
    o.x = pack_h2(tanh_fast(ev.x + pv.x), tanh_fast(ev.y + pv.y));
    o.y = pack_h2(tanh_fast(ev.z + pv.z), tanh_fast(ev.w + pv.w));
    *(uint2*)(g_Ah + ((size_t)m << 10) + kc) = o;
}

// ================= kernel 4: pure fp16 GEMM  out = A_h @ Wt^T + bias =================
// CTA tile 128(M) x 256(N), K=1024 in 32 chunks of 32. 8 warps (2M x 4N), warp 64x64.
// 4-stage cp.async pipeline, both operands async.
constexpr int ARSTR = 80;                        // bytes per A smem row (64B data + pad)
constexpr int BRSTR = 80;
constexpr int ABYTES = 128 * ARSTR;              // 10240
constexpr int BBYTES = 256 * BRSTR;              // 20480
constexpr int STG_BYTES = ABYTES + BBYTES;       // 30720
constexpr int NSTAGE = 4;
constexpr int OFF_STG = 1024;
constexpr int FUSED_SMEM = OFF_STG + NSTAGE * STG_BYTES;  // 123904

__global__ __launch_bounds__(256, 1) void gemm_kernel(
    const float* __restrict__ b_out, float* __restrict__ out) {
    extern __shared__ char smem[];
    uint32_t sb = smem_u32(smem);
    float* bias_s = (float*)smem;

    int tid = threadIdx.x;
    int lane = tid & 31;
    int wid = tid >> 5;
    int wm = wid >> 2;        // 0..1
    int wn = wid & 3;         // 0..3

    int n0 = blockIdx.x << 8;          // N-tile (fast dim -> A reuse in L2)
    int m0 = blockIdx.y << 7;          // M-tile

    bias_s[tid] = b_out[n0 + tid];

    // ---- producer addressing ----
    // A: 512 granules of 16B per chunk; thread handles granules {tid, tid+256}
    int ar0 = tid >> 2, aq0 = tid & 3;
    const __half* asrc0 = g_Ah + ((size_t)(m0 + ar0) << 10) + aq0 * 8;
    const __half* asrc1 = g_Ah + ((size_t)(m0 + 64 + ar0) << 10) + aq0 * 8;
    uint32_t a_sts0 = (uint32_t)ar0 * ARSTR + aq0 * 16;
    uint32_t a_sts1 = (uint32_t)(64 + ar0) * ARSTR + aq0 * 16;
    // B: 1024 granules; thread handles 4 (rows tid>>2 + 64j)
    const __half* bsrc = g_Wth + ((size_t)(n0 + (tid >> 2)) << 10) + (tid & 3) * 8;
    uint32_t b_sts = ABYTES + (uint32_t)(tid >> 2) * BRSTR + (tid & 3) * 16;

    // ---- consumer LDSM per-lane offsets ----
    uint32_t a_off[4], b_off[4];
#pragma unroll
    for (int mt = 0; mt < 4; ++mt) {
        int row = wm * 64 + mt * 16 + (lane & 15);
        a_off[mt] = (uint32_t)row * ARSTR + (uint32_t)(lane >> 4) * 16;
    }
#pragma unroll
    for (int g = 0; g < 4; ++g) {
        int row = wn * 64 + g * 16 + (lane & 7) + ((lane >> 4) & 1) * 8;
        b_off[g] = ABYTES + (uint32_t)row * BRSTR + (uint32_t)((lane >> 3) & 1) * 16;
    }

    float acc[4][8][4];
#pragma unroll
    for (int mt = 0; mt < 4; ++mt)
#pragma unroll
        for (int nt = 0; nt < 8; ++nt)
#pragma unroll
            for (int q = 0; q < 4; ++q) acc[mt][nt][q] = 0.0f;

    // ---- prologue: stage chunks 0..NSTAGE-2 ----
#pragma unroll
    for (int pc = 0; pc < NSTAGE - 1; ++pc) {
        uint32_t st = sb + OFF_STG + pc * STG_BYTES;
        int k0 = pc << 5;
        cp_async16(st + a_sts0, asrc0 + k0);
        cp_async16(st + a_sts1, asrc1 + k0);
#pragma unroll
        for (int j = 0; j < 4; ++j)
            cp_async16(st + b_sts + j * 64 * BRSTR, bsrc + k0 + (size_t)j * 64 * Jdim);
        cp_commit();
    }

    // ---- main loop ----
#pragma unroll 1
    for (int c = 0; c < 32; ++c) {
        int s = c & (NSTAGE - 1);
        cp_wait2();          // chunk c resident (all but 2 newest groups done)
        __syncthreads();

        if (c + NSTAGE - 1 < 32) {
            int cn = c + NSTAGE - 1;
            uint32_t st = sb + OFF_STG + (cn & (NSTAGE - 1)) * STG_BYTES;
            int k0 = cn << 5;
            cp_async16(st + a_sts0, asrc0 + k0);
            cp_async16(st + a_sts1, asrc1 + k0);
#pragma unroll
            for (int j = 0; j < 4; ++j)
                cp_async16(st + b_sts + j * 64 * BRSTR, bsrc + k0 + (size_t)j * 64 * Jdim);
        }
        cp_commit();         // commit every iter (possibly empty) to keep group math valid

        uint32_t stage = sb + OFF_STG + s * STG_BYTES;
#pragma unroll
        for (int ks = 0; ks < 2; ++ks) {
            uint32_t a[4][4], b[4][4];
#pragma unroll
            for (int mt = 0; mt < 4; ++mt)
                ldsm_x4(a[mt][0], a[mt][1], a[mt][2], a[mt][3],
                        stage + a_off[mt] + ks * 32);
#pragma unroll
            for (int g = 0; g < 4; ++g)
                ldsm_x4(b[g][0], b[g][1], b[g][2], b[g][3],
                        stage + b_off[g] + ks * 32);
#pragma unroll
            for (int mt = 0; mt < 4; ++mt) {
#pragma unroll
                for (int g = 0; g < 4; ++g) {
                    mma_fp16(acc[mt][g * 2][0], acc[mt][g * 2][1],
                             acc[mt][g * 2][2], acc[mt][g * 2][3],
                             a[mt][0], a[mt][1], a[mt][2], a[mt][3],
                             b[g][0], b[g][1]);
                    mma_fp16(acc[mt][g * 2 + 1][0], acc[mt][g * 2 + 1][1],
                             acc[mt][g * 2 + 1][2], acc[mt][g * 2 + 1][3],
                             a[mt][0], a[mt][1], a[mt][2], a[mt][3],
                             b[g][2], b[g][3]);
                }
            }
        }
    }

    // ---- epilogue: bias + store ----
    int gr = lane >> 2, gc2 = (lane & 3) * 2;
    const float* bias_w = bias_s + wn * 64;
#pragma unroll
    for (int mt = 0; mt < 4; ++mt) {
#pragma unroll
        for (int half = 0; half < 2; ++half) {
            int row = m0 + wm * 64 + mt * 16 + gr + half * 8;
            float* orow = out + (size_t)row * Vdim + n0 + wn * 64;
#pragma unroll
            for (int nt = 0; nt < 8; ++nt) {
                int col = nt * 8 + gc2;
                float2 v;
                v.x = acc[mt][nt][half * 2 + 0] + bias_w[col];
                v.y = acc[mt][nt][half * 2 + 1] + bias_w[col + 1];
                *(float2*)(orow + col) = v;
            }
        }
    }
}

// ================= launch =================
extern "C" void kernel_launch(void* const* d_in, const int* in_sizes, int n_in,
                              void* d_out, int out_size) {
    const float* enc    = (const float*)d_in[0];
    const float* pred   = (const float*)d_in[1];
    const float* W_enc  = (const float*)d_in[2];
    const float* b_enc  = (const float*)d_in[3];
    const float* W_pred = (const float*)d_in[4];
    const float* b_pred = (const float*)d_in[5];
    const float* W_out  = (const float*)d_in[6];
    const float* b_out  = (const float*)d_in[7];
    float* out = (float*)d_out;

    cudaFuncSetAttribute(gemm_kernel,
                         cudaFuncAttributeMaxDynamicSharedMemorySize, FUSED_SMEM);

    // enc_out = enc @ W_enc + b_enc : M = B*T = 1024
    proj_kernel<<<dim3(Jdim / 64, 1024 / 64), 256>>>(enc, W_enc, b_enc, 0);
    // pred_out = pred @ W_pred + b_pred : M = B*U = 256
    proj_kernel<<<dim3(Jdim / 64, 256 / 64), 256>>>(pred, W_pred, b_pred, 1);
    // Wt fp16 = W_out^T
    transpose_h_kernel<<<dim3(Vdim / 32, Jdim / 32), 256>>>(W_out);
    // A_h = fp16(tanh(enc_out (+) pred_out))  [65536, 1024]
    tanh_pre_kernel<<<65536, 256>>>();
    // pure fp16 GEMM (n-tile fastest for A L2 reuse)
    gemm_kernel<<<dim3(4, 512), 256, FUSED_SMEM>>>(b_out, out);
}